// round 1
// baseline (speedup 1.0000x reference)
#include <cuda_runtime.h>

#define N_NODES 50000
#define E_EDGES 1600000
#define IN_F    256
#define AD      128
#define H_HEADS 8
// DK = 16, scale = 1/sqrt(16) = 0.25

// Scratch (device globals — no allocation allowed)
__device__ float g_q[N_NODES * AD];       // 25.6 MB
__device__ float g_k[N_NODES * AD];       // 25.6 MB
__device__ float g_s[N_NODES * H_HEADS];  // 1.6 MB softmax denominators

// ---------------------------------------------------------------------------
// Zero the per-(node,head) exp-sum accumulator
// ---------------------------------------------------------------------------
__global__ void zero_s_kernel() {
    int i = blockIdx.x * blockDim.x + threadIdx.x;
    if (i < N_NODES * H_HEADS) g_s[i] = 0.0f;
}

// ---------------------------------------------------------------------------
// Fused Q/K projection:  out[N, 256] = hi @ [Qw;Kw]^T + [Qb;Kb]
// Tiled fp32 SIMT GEMM. BM=64, BN=64, BK=16, 256 threads, 4x4 per thread.
// grid.y: 0,1 -> Q cols [0,64),[64,128);  2,3 -> K cols.
// ---------------------------------------------------------------------------
#define BM 64
#define BN 64
#define BK 16
#define PAD 4   // row stride 68 floats = 272 B (multiple of 16 B -> float4-safe)

__global__ __launch_bounds__(256) void gemm_qk_kernel(
    const float* __restrict__ hi,
    const float* __restrict__ Qw, const float* __restrict__ Qb,
    const float* __restrict__ Kw, const float* __restrict__ Kb)
{
    __shared__ float As[BK][BM + PAD];
    __shared__ float Bs[BK][BN + PAD];

    const int tid = threadIdx.x;
    const int tx  = tid & 15;        // 0..15 -> n micro-tile
    const int ty  = tid >> 4;        // 0..15 -> m micro-tile
    const int m0  = blockIdx.x * BM;
    const int n0c = blockIdx.y * BN; // combined col 0..255
    const bool isK = (n0c >= AD);
    const float* W    = isK ? Kw : Qw;
    const float* bias = isK ? Kb : Qb;
    const int n0      = isK ? (n0c - AD) : n0c;   // 0 or 64
    float* outp       = isK ? g_k : g_q;

    float acc[4][4];
    {
        float4 b4 = *(const float4*)&bias[n0 + tx * 4];
        #pragma unroll
        for (int i = 0; i < 4; i++) {
            acc[i][0] = b4.x; acc[i][1] = b4.y; acc[i][2] = b4.z; acc[i][3] = b4.w;
        }
    }

    const int lrow = tid >> 2;         // 0..63
    const int lc4  = (tid & 3) * 4;    // 0,4,8,12

    for (int k0 = 0; k0 < IN_F; k0 += BK) {
        // A tile: hi[m0+lrow][k0+lc4 .. +3]  (transposed into As[k][m])
        float4 av = make_float4(0.f, 0.f, 0.f, 0.f);
        const int gm = m0 + lrow;
        if (gm < N_NODES)
            av = *(const float4*)&hi[(size_t)gm * IN_F + k0 + lc4];
        As[lc4 + 0][lrow] = av.x;
        As[lc4 + 1][lrow] = av.y;
        As[lc4 + 2][lrow] = av.z;
        As[lc4 + 3][lrow] = av.w;
        // B tile: W[n0+lrow][k0+lc4 .. +3]  (transposed into Bs[k][n])
        float4 bv = *(const float4*)&W[(size_t)(n0 + lrow) * IN_F + k0 + lc4];
        Bs[lc4 + 0][lrow] = bv.x;
        Bs[lc4 + 1][lrow] = bv.y;
        Bs[lc4 + 2][lrow] = bv.z;
        Bs[lc4 + 3][lrow] = bv.w;
        __syncthreads();

        #pragma unroll
        for (int k = 0; k < BK; k++) {
            float4 a4 = *(const float4*)&As[k][ty * 4];
            float4 b4 = *(const float4*)&Bs[k][tx * 4];
            float a[4] = {a4.x, a4.y, a4.z, a4.w};
            float b[4] = {b4.x, b4.y, b4.z, b4.w};
            #pragma unroll
            for (int i = 0; i < 4; i++)
                #pragma unroll
                for (int j = 0; j < 4; j++)
                    acc[i][j] += a[i] * b[j];
        }
        __syncthreads();
    }

    #pragma unroll
    for (int i = 0; i < 4; i++) {
        const int gm = m0 + ty * 4 + i;
        if (gm < N_NODES) {
            float4 v = make_float4(acc[i][0], acc[i][1], acc[i][2], acc[i][3]);
            *(float4*)&outp[(size_t)gm * AD + n0 + tx * 4] = v;
        }
    }
}

// ---------------------------------------------------------------------------
// Edge kernel: one warp per edge.
//   lane i owns floats [4i, 4i+4) of the 128-dim vectors (head = i/4, DK=16).
//   prods[e,h] = dot(q[src]+radial*Qrw+Qrb, k[dst]) / 4
//   writes prods, writes exp(prods) into attention slot, atomicAdd to g_s.
// ---------------------------------------------------------------------------
__global__ __launch_bounds__(256) void edge_kernel(
    const int*   __restrict__ edge0,
    const int*   __restrict__ edge1,
    const float* __restrict__ radial,
    const float* __restrict__ Qrw,
    const float* __restrict__ Qrb,
    float* __restrict__ out_att,
    float* __restrict__ out_prods)
{
    const int warp = threadIdx.x >> 5;
    const int lane = threadIdx.x & 31;
    const int e = blockIdx.x * 8 + warp;
    if (e >= E_EDGES) return;

    // Per-lane radial projection constants (128 floats each, L1-resident)
    const float4 w4 = *(const float4*)&Qrw[lane * 4];
    const float4 b4 = *(const float4*)&Qrb[lane * 4];

    const int src = edge0[e];
    const int dst = edge1[e];
    const float r = radial[e];

    const float4 q4 = *(const float4*)&g_q[(size_t)src * AD + lane * 4];
    const float4 k4 = *(const float4*)&g_k[(size_t)dst * AD + lane * 4];

    const float sx = fmaf(r, w4.x, q4.x + b4.x);
    const float sy = fmaf(r, w4.y, q4.y + b4.y);
    const float sz = fmaf(r, w4.z, q4.z + b4.z);
    const float sw = fmaf(r, w4.w, q4.w + b4.w);

    float p = sx * k4.x + sy * k4.y + sz * k4.z + sw * k4.w;
    // reduce within each quad of lanes (one head = 4 lanes)
    p += __shfl_xor_sync(0xFFFFFFFFu, p, 1);
    p += __shfl_xor_sync(0xFFFFFFFFu, p, 2);
    p *= 0.25f;   // 1/sqrt(DK)

    // compact: lane h (0..7) grabs head value from lane 4h
    const float ph = __shfl_sync(0xFFFFFFFFu, p, (lane * 4) & 31);
    if (lane < H_HEADS) {
        out_prods[(size_t)e * H_HEADS + lane] = ph;
        const float ex = __expf(ph);
        out_att[(size_t)e * H_HEADS + lane] = ex;
        atomicAdd(&g_s[src * H_HEADS + lane], ex);
    }
}

// ---------------------------------------------------------------------------
// Normalize: attention = exp(p) / sum_exp[segment]
// ---------------------------------------------------------------------------
__global__ __launch_bounds__(256) void norm_kernel(
    const int* __restrict__ edge0,
    float* __restrict__ out_att)
{
    const int i = blockIdx.x * blockDim.x + threadIdx.x;
    if (i >= E_EDGES * H_HEADS) return;
    const int e = i >> 3;
    const int h = i & 7;
    out_att[i] = out_att[i] / g_s[edge0[e] * H_HEADS + h];
}

// ---------------------------------------------------------------------------
// Launch
// Inputs (metadata order): hi, radial, Qw, Qb, Qrw, Qrb, Kw, Kb, edge
// Output: [attention (E*H) | prods (E*H)] fp32
// ---------------------------------------------------------------------------
extern "C" void kernel_launch(void* const* d_in, const int* in_sizes, int n_in,
                              void* d_out, int out_size)
{
    const float* hi     = (const float*)d_in[0];
    const float* radial = (const float*)d_in[1];
    const float* Qw     = (const float*)d_in[2];
    const float* Qb     = (const float*)d_in[3];
    const float* Qrw    = (const float*)d_in[4];
    const float* Qrb    = (const float*)d_in[5];
    const float* Kw     = (const float*)d_in[6];
    const float* Kb     = (const float*)d_in[7];
    const int*   edge   = (const int*)d_in[8];
    const int*   edge0  = edge;
    const int*   edge1  = edge + E_EDGES;

    float* out_att   = (float*)d_out;
    float* out_prods = out_att + (size_t)E_EDGES * H_HEADS;

    // 1. zero softmax denominators
    zero_s_kernel<<<(N_NODES * H_HEADS + 255) / 256, 256>>>();

    // 2. Q/K projections
    dim3 ggrid((N_NODES + BM - 1) / BM, 256 / BN);  // 782 x 4
    gemm_qk_kernel<<<ggrid, 256>>>(hi, Qw, Qb, Kw, Kb);

    // 3. per-edge dot + exp + segment sums (1 warp / edge, 8 warps / block)
    edge_kernel<<<(E_EDGES + 7) / 8, 256>>>(edge0, edge1, radial, Qrw, Qrb,
                                            out_att, out_prods);

    // 4. normalize
    norm_kernel<<<(E_EDGES * H_HEADS + 255) / 256, 256>>>(edge0, out_att);
}